// round 4
// baseline (speedup 1.0000x reference)
#include <cuda_runtime.h>
#include <cstdint>

// CSpace resonator bank as 1st-order complex IIR.
// Block = one (b,c,dir) sequence. 3 rounds x 160 thread-chunks x 100 samples.
// Phase A: chunk-run from zero -> affine sums; block scan -> exact entry states;
// Phase B: re-run chunks from entry states, writing outputs.

#define TT 48000
#define CC 64
#define BB 8
#define KLEN 24000
#define NT 160
#define NWARPS 5
#define RNDS 3
#define LCH 100
#define RSAMP (NT * LCH)   // 16000 per round; 3*16000 = 48000

__device__ __forceinline__ void cmulD(double& ar, double& ai, double br, double bi) {
    double t = ar * br - ai * bi;
    ai = ar * bi + ai * br;
    ar = t;
}

template <bool REV>
__device__ __forceinline__ void run_seq(const float* __restrict__ x,
                                        float* __restrict__ out_re,
                                        float* __restrict__ out_im,
                                        double der, double dei,
                                        float gr, float gi,
                                        float2* __restrict__ s_tot)
{
    const int tid  = threadIdx.x;
    const int lane = tid & 31;
    const int w    = tid >> 5;
    const unsigned FULL = 0xFFFFFFFFu;

    // ---- double-precision constant setup ----
    // e^(2^k), k=0..6
    double Er[7], Ei[7];
    Er[0] = der; Ei[0] = dei;
    #pragma unroll
    for (int k = 1; k < 7; ++k) { Er[k] = Er[k-1]; Ei[k] = Ei[k-1]; cmulD(Er[k], Ei[k], Er[k-1], Ei[k-1]); }
    // ELc = e^100 = e^64 * e^32 * e^4
    double Lr = Er[6], Li = Ei[6];
    cmulD(Lr, Li, Er[5], Ei[5]);
    cmulD(Lr, Li, Er[2], Ei[2]);
    // ELc^(2^k), k=0..7
    double Pr8[8], Pi8[8];
    Pr8[0] = Lr; Pi8[0] = Li;
    #pragma unroll
    for (int k = 1; k < 8; ++k) { Pr8[k] = Pr8[k-1]; Pi8[k] = Pi8[k-1]; cmulD(Pr8[k], Pi8[k], Pr8[k-1], Pi8[k-1]); }
    // EW = ELc^32 ; EF = ELc^160 = ELc^128 * ELc^32
    double EWdr = Pr8[5], EWdi = Pi8[5];
    double EFdr = Pr8[7], EFdi = Pi8[7];
    cmulD(EFdr, EFdi, Pr8[5], Pi8[5]);
    // ql = ELc^lane ; Qt = ELc^tid
    double qdr = 1.0, qdi = 0.0;
    #pragma unroll
    for (int k = 0; k < 5; ++k) if ((lane >> k) & 1) cmulD(qdr, qdi, Pr8[k], Pi8[k]);
    double Qdr = 1.0, Qdi = 0.0;
    #pragma unroll
    for (int k = 0; k < 8; ++k) if ((tid >> k) & 1) cmulD(Qdr, Qdi, Pr8[k], Pi8[k]);

    const float er = (float)der, ei = (float)dei;
    const float c0r=(float)Pr8[0], c0i=(float)Pi8[0];
    const float c1r=(float)Pr8[1], c1i=(float)Pi8[1];
    const float c2r=(float)Pr8[2], c2i=(float)Pi8[2];
    const float c3r=(float)Pr8[3], c3i=(float)Pi8[3];
    const float c4r=(float)Pr8[4], c4i=(float)Pi8[4];
    const float EWr=(float)EWdr, EWi=(float)EWdi;
    const float EFr=(float)EFdr, EFi=(float)EFdi;
    const float qlr=(float)qdr,  qli=(float)qdi;
    const float Qtr=(float)Qdr,  Qti=(float)Qdi;

    float pr = 0.f, pi = 0.f;   // sequence state at round start

    for (int r = 0; r < RNDS; ++r) {
        const int base = r * RSAMP + tid * LCH;

        // ---- Phase A: chunk from zero state ----
        float yr = 0.f, yi = 0.f;
        {
            float4 X = REV ? *reinterpret_cast<const float4*>(x + (TT - 4 - base))
                           : *reinterpret_cast<const float4*>(x + base);
            #pragma unroll 5
            for (int i = 0; i < LCH / 4; ++i) {
                float4 Xn;
                if (i + 1 < LCH / 4) {
                    int sb = base + (i + 1) * 4;
                    Xn = REV ? *reinterpret_cast<const float4*>(x + (TT - 4 - sb))
                             : *reinterpret_cast<const float4*>(x + sb);
                }
                float x0, x1, x2, x3;
                if (!REV) { x0=X.x; x1=X.y; x2=X.z; x3=X.w; }
                else      { x0=X.w; x1=X.z; x2=X.y; x3=X.x; }
                float tr, ti;
                tr = er*yr - ei*yi + gr*x0; ti = er*yi + ei*yr + gi*x0; yr=tr; yi=ti;
                tr = er*yr - ei*yi + gr*x1; ti = er*yi + ei*yr + gi*x1; yr=tr; yi=ti;
                tr = er*yr - ei*yi + gr*x2; ti = er*yi + ei*yr + gi*x2; yr=tr; yi=ti;
                tr = er*yr - ei*yi + gr*x3; ti = er*yi + ei*yr + gi*x3; yr=tr; yi=ti;
                X = Xn;
            }
        }

        // ---- scan: entry_j = Qt*p + exclusive-prefix of C with ratio ELc ----
        float sr = yr, si = yi;
        { float ur=__shfl_up_sync(FULL,sr,1),  ui=__shfl_up_sync(FULL,si,1);
          if (lane>=1)  { sr += c0r*ur - c0i*ui; si += c0r*ui + c0i*ur; } }
        { float ur=__shfl_up_sync(FULL,sr,2),  ui=__shfl_up_sync(FULL,si,2);
          if (lane>=2)  { sr += c1r*ur - c1i*ui; si += c1r*ui + c1i*ur; } }
        { float ur=__shfl_up_sync(FULL,sr,4),  ui=__shfl_up_sync(FULL,si,4);
          if (lane>=4)  { sr += c2r*ur - c2i*ui; si += c2r*ui + c2i*ur; } }
        { float ur=__shfl_up_sync(FULL,sr,8),  ui=__shfl_up_sync(FULL,si,8);
          if (lane>=8)  { sr += c3r*ur - c3i*ui; si += c3r*ui + c3i*ur; } }
        { float ur=__shfl_up_sync(FULL,sr,16), ui=__shfl_up_sync(FULL,si,16);
          if (lane>=16) { sr += c4r*ur - c4i*ui; si += c4r*ui + c4i*ur; } }

        float hr = __shfl_up_sync(FULL, sr, 1);
        float hi = __shfl_up_sync(FULL, si, 1);
        if (lane == 0) { hr = 0.f; hi = 0.f; }

        float2* tot = s_tot + (r & 1) * 8;
        if (lane == 31) tot[w] = make_float2(sr, si);
        __syncthreads();

        // serial combine over 5 warp totals: P_{v+1} = T_v + EW*P_v
        float Pwr = 0.f, Pwi = 0.f;       // P_w for my warp
        float Pr_ = 0.f, Pi_ = 0.f;
        #pragma unroll
        for (int v = 0; v < NWARPS; ++v) {
            if (v == w) { Pwr = Pr_; Pwi = Pi_; }
            float2 T = tot[v];
            float nr = T.x + EWr*Pr_ - EWi*Pi_;
            float ni = T.y + EWr*Pi_ + EWi*Pr_;
            Pr_ = nr; Pi_ = ni;
        }
        // Pr_ now = X_160 (block total); Pw = warp-exclusive prefix
        float entr = hr + qlr*Pwr - qli*Pwi + Qtr*pr - Qti*pi;
        float enti = hi + qlr*Pwi + qli*Pwr + Qtr*pi + Qti*pr;

        float npr = Pr_ + EFr*pr - EFi*pi;
        float npi = Pi_ + EFr*pi + EFi*pr;

        // ---- Phase B: re-run chunk from exact entry state, write outputs ----
        yr = entr; yi = enti;
        {
            float4 X = REV ? *reinterpret_cast<const float4*>(x + (TT - 4 - base))
                           : *reinterpret_cast<const float4*>(x + base);
            #pragma unroll 5
            for (int i = 0; i < LCH / 4; ++i) {
                float4 Xn;
                if (i + 1 < LCH / 4) {
                    int sb = base + (i + 1) * 4;
                    Xn = REV ? *reinterpret_cast<const float4*>(x + (TT - 4 - sb))
                             : *reinterpret_cast<const float4*>(x + sb);
                }
                float x0, x1, x2, x3;
                if (!REV) { x0=X.x; x1=X.y; x2=X.z; x3=X.w; }
                else      { x0=X.w; x1=X.z; x2=X.y; x3=X.x; }
                float tr, ti;
                float o0r,o0i,o1r,o1i,o2r,o2i,o3r,o3i;
                tr = er*yr - ei*yi + gr*x0; ti = er*yi + ei*yr + gi*x0; yr=tr; yi=ti; o0r=yr; o0i=yi;
                tr = er*yr - ei*yi + gr*x1; ti = er*yi + ei*yr + gi*x1; yr=tr; yi=ti; o1r=yr; o1i=yi;
                tr = er*yr - ei*yi + gr*x2; ti = er*yi + ei*yr + gi*x2; yr=tr; yi=ti; o2r=yr; o2i=yi;
                tr = er*yr - ei*yi + gr*x3; ti = er*yi + ei*yr + gi*x3; yr=tr; yi=ti; o3r=yr; o3i=yi;

                int sb = base + i * 4;
                if (!REV) {
                    *reinterpret_cast<float4*>(out_re + sb) = make_float4(o0r,o1r,o2r,o3r);
                    *reinterpret_cast<float4*>(out_im + sb) = make_float4(o0i,o1i,o2i,o3i);
                } else {
                    *reinterpret_cast<float4*>(out_re + (TT - 4 - sb)) = make_float4(o3r,o2r,o1r,o0r);
                    *reinterpret_cast<float4*>(out_im + (TT - 4 - sb)) = make_float4(o3i,o2i,o1i,o0i);
                }
                X = Xn;
            }
        }

        pr = npr; pi = npi;
    }
}

__global__ void __launch_bounds__(NT, 7)
cspace_iir_kernel(const float* __restrict__ audio,
                  const float* __restrict__ kre,
                  const float* __restrict__ kim,
                  float* __restrict__ out)
{
    __shared__ float2 s_tot[16];   // double-buffered 5-warp totals (padded)

    int blk = blockIdx.x;          // [0, 1024)
    int dir = blk & 1;
    int c   = (blk >> 1) & 63;
    int b   = blk >> 7;

    float k0r = kre[c * KLEN + 0], k0i = kim[c * KLEN + 0];
    float k1r = kre[c * KLEN + 1], k1i = kim[c * KLEN + 1];
    double inv = 1.0 / ((double)k0r * k0r + (double)k0i * k0i);
    double der = ((double)k1r * k0r + (double)k1i * k0i) * inv;
    double dei = ((double)k1i * k0r - (double)k1r * k0i) * inv;
    float gr = k0r, gi = k0i;

    const float* x = audio + (size_t)b * TT;
    float* base = out + (size_t)b * 4 * CC * TT;

    if (dir == 0) {
        run_seq<false>(x, base + (size_t)c * TT,
                          base + (size_t)(CC + c) * TT, der, dei, gr, gi, s_tot);
    } else {
        run_seq<true>(x,  base + (size_t)(2 * CC + c) * TT,
                          base + (size_t)(3 * CC + c) * TT, der, dei, gr, gi, s_tot);
    }
}

extern "C" void kernel_launch(void* const* d_in, const int* in_sizes, int n_in,
                              void* d_out, int out_size)
{
    const float* audio = (const float*)d_in[0];
    const float* kre   = (const float*)d_in[1];
    const float* kim   = (const float*)d_in[2];
    float* out = (float*)d_out;
    (void)in_sizes; (void)n_in; (void)out_size;

    cspace_iir_kernel<<<BB * CC * 2, NT>>>(audio, kre, kim, out);
}

// round 6
// speedup vs baseline: 3.5810x; 3.5810x over previous
#include <cuda_runtime.h>
#include <cstdint>

// CSpace resonator bank as 1st-order complex IIR, split-scan over time slices.
// 1024 sequences x 25 slices of 1920 samples; warp per slice.
// Kernel A: slice affine totals (no outputs). Kernel C: fold entry + replay w/ outputs.

#define TT 48000
#define CC 64
#define BB 8
#define KLEN 24000
#define NSLICE 25
#define SLEN 1920
#define NITERS 15           // 15 * 128 = 1920
#define NSEQ (BB * CC * 2)  // 1024
#define NWORK (NSEQ * NSLICE) // 25600
#define WPB 8               // warps per block
#define NBLK (NWORK / WPB)  // 3200

__device__ float2 g_tot[NWORK];
// per-channel table: [0..7] e^1..e^4 (re,im), [8..17] A_k=E4^(2^k) k=0..4,
// [18..19] E128, [20..21] E1920, [22..23] g
__device__ float g_ctab[CC][24];

__device__ __forceinline__ void cmulD(double& ar, double& ai, double br, double bi) {
    double t = ar * br - ai * bi;
    ai = ar * bi + ai * br;
    ar = t;
}

__global__ void kprep(const float* __restrict__ kre, const float* __restrict__ kim) {
    int c = threadIdx.x;
    if (c >= CC) return;
    double k0r = kre[c * KLEN + 0], k0i = kim[c * KLEN + 0];
    double k1r = kre[c * KLEN + 1], k1i = kim[c * KLEN + 1];
    double inv = 1.0 / (k0r * k0r + k0i * k0i);
    double er = (k1r * k0r + k1i * k0i) * inv;
    double ei = (k1i * k0r - k1r * k0i) * inv;

    double e2r = er, e2i = ei;  cmulD(e2r, e2i, er, ei);
    double e3r = e2r, e3i = e2i; cmulD(e3r, e3i, er, ei);
    double e4r = e2r, e4i = e2i; cmulD(e4r, e4i, e2r, e2i);

    double Ar[6], Ai[6];
    Ar[0] = e4r; Ai[0] = e4i;
    #pragma unroll
    for (int k = 1; k < 6; ++k) { Ar[k] = Ar[k-1]; Ai[k] = Ai[k-1]; cmulD(Ar[k], Ai[k], Ar[k-1], Ai[k-1]); }
    // A[5] = E4^32 = E128
    // E1920 = E128^15 = C0*C1*C2*C3 with C_k = E128^(2^k)
    double Cr[4], Ci[4];
    Cr[0] = Ar[5]; Ci[0] = Ai[5];
    #pragma unroll
    for (int k = 1; k < 4; ++k) { Cr[k] = Cr[k-1]; Ci[k] = Ci[k-1]; cmulD(Cr[k], Ci[k], Cr[k-1], Ci[k-1]); }
    double Fr = Cr[0], Fi = Ci[0];
    cmulD(Fr, Fi, Cr[1], Ci[1]);
    cmulD(Fr, Fi, Cr[2], Ci[2]);
    cmulD(Fr, Fi, Cr[3], Ci[3]);

    float* t = g_ctab[c];
    t[0] = (float)er;  t[1] = (float)ei;
    t[2] = (float)e2r; t[3] = (float)e2i;
    t[4] = (float)e3r; t[5] = (float)e3i;
    t[6] = (float)e4r; t[7] = (float)e4i;
    #pragma unroll
    for (int k = 0; k < 5; ++k) { t[8 + 2*k] = (float)Ar[k]; t[9 + 2*k] = (float)Ai[k]; }
    t[18] = (float)Ar[5]; t[19] = (float)Ai[5];
    t[20] = (float)Fr;    t[21] = (float)Fi;
    t[22] = (float)k0r;   t[23] = (float)k0i;
}

// ---------------- Kernel A: slice totals ----------------
template <bool REV>
__device__ __forceinline__ void sliceA(const float* __restrict__ x, int j, int lane,
                                       const float* __restrict__ tb, int W)
{
    const unsigned FULL = 0xFFFFFFFFu;
    const float er = tb[0], ei = tb[1];
    const float e128r = tb[18], e128i = tb[19];
    const float gr = tb[22], gi = tb[23];

    // weight = E4^(31-lane) via float binary exponentiation over A_k
    float wr = 1.f, wi = 0.f;
    {
        int p = 31 - lane;
        #pragma unroll
        for (int k = 0; k < 5; ++k)
            if ((p >> k) & 1) {
                float ar = tb[8 + 2*k], ai = tb[9 + 2*k];
                float nr = wr*ar - wi*ai, ni = wr*ai + wi*ar;
                wr = nr; wi = ni;
            }
    }

    float Xr = 0.f, Xi = 0.f;
    #pragma unroll 5
    for (int i = 0; i < NITERS; ++i) {
        int n0 = j * SLEN + i * 128 + lane * 4;
        float4 v = REV ? *reinterpret_cast<const float4*>(x + (TT - 4 - n0))
                       : *reinterpret_cast<const float4*>(x + n0);
        float x0, x1, x2, x3;
        if (!REV) { x0=v.x; x1=v.y; x2=v.z; x3=v.w; }
        else      { x0=v.w; x1=v.z; x2=v.y; x3=v.x; }

        float yr = gr*x0, yi = gi*x0, tr, ti;
        tr = er*yr - ei*yi + gr*x1; ti = er*yi + ei*yr + gi*x1; yr=tr; yi=ti;
        tr = er*yr - ei*yi + gr*x2; ti = er*yi + ei*yr + gi*x2; yr=tr; yi=ti;
        tr = er*yr - ei*yi + gr*x3; ti = er*yi + ei*yr + gi*x3; yr=tr; yi=ti;

        float sr = wr*yr - wi*yi;
        float si = wr*yi + wi*yr;
        #pragma unroll
        for (int d = 16; d >= 1; d >>= 1) {
            sr += __shfl_xor_sync(FULL, sr, d);
            si += __shfl_xor_sync(FULL, si, d);
        }
        float nXr = sr + e128r*Xr - e128i*Xi;
        float nXi = si + e128r*Xi + e128i*Xr;
        Xr = nXr; Xi = nXi;
    }
    if (lane == 0) g_tot[W] = make_float2(Xr, Xi);
}

__global__ void __launch_bounds__(WPB * 32)
kA(const float* __restrict__ audio)
{
    int lane = threadIdx.x & 31;
    int W = blockIdx.x * WPB + (threadIdx.x >> 5);
    int s = W / NSLICE;
    int j = W - s * NSLICE;
    int dir = s & 1, c = (s >> 1) & 63, b = s >> 7;

    const float* tb = g_ctab[c];
    const float* x = audio + (size_t)b * TT;
    if (dir == 0) sliceA<false>(x, j, lane, tb, W);
    else          sliceA<true >(x, j, lane, tb, W);
}

// ---------------- Kernel C: outputs ----------------
template <bool REV>
__device__ __forceinline__ void sliceC(const float* __restrict__ x,
                                       float* __restrict__ out_re,
                                       float* __restrict__ out_im,
                                       int s, int j, int lane,
                                       const float* __restrict__ tb)
{
    const unsigned FULL = 0xFFFFFFFFu;
    const float er  = tb[0],  eic = tb[1];
    const float e2r = tb[2],  e2i = tb[3];
    const float e3r = tb[4],  e3i = tb[5];
    const float e4r = tb[6],  e4i = tb[7];
    const float a0r = tb[8],  a0i = tb[9];
    const float a1r = tb[10], a1i = tb[11];
    const float a2r = tb[12], a2i = tb[13];
    const float a3r = tb[14], a3i = tb[15];
    const float a4r = tb[16], a4i = tb[17];
    const float e128r = tb[18], e128i = tb[19];
    const float f19r  = tb[20], f19i  = tb[21];
    const float gr = tb[22], gi = tb[23];

    // q = E4^lane
    float qr = 1.f, qi = 0.f;
    #pragma unroll
    for (int k = 0; k < 5; ++k)
        if ((lane >> k) & 1) {
            float ar = tb[8 + 2*k], ai = tb[9 + 2*k];
            float nr = qr*ar - qi*ai, ni = qr*ai + qi*ar;
            qr = nr; qi = ni;
        }

    // fold predecessor slice totals -> entry state (uniform loads, all lanes)
    float inr = 0.f, ini = 0.f;
    const float2* tot = &g_tot[s * NSLICE];
    for (int t = 0; t < j; ++t) {
        float2 v = tot[t];
        float nr = v.x + f19r*inr - f19i*ini;
        float ni = v.y + f19r*ini + f19i*inr;
        inr = nr; ini = ni;
    }

    #pragma unroll 3
    for (int i = 0; i < NITERS; ++i) {
        int n0 = j * SLEN + i * 128 + lane * 4;
        float4 v = REV ? *reinterpret_cast<const float4*>(x + (TT - 4 - n0))
                       : *reinterpret_cast<const float4*>(x + n0);
        float x0, x1, x2, x3;
        if (!REV) { x0=v.x; x1=v.y; x2=v.z; x3=v.w; }
        else      { x0=v.w; x1=v.z; x2=v.y; x3=v.x; }

        // local partials from zero (kept for output reconstruction)
        float c1r = gr*x0, c1i = gi*x0;
        float c2r = er*c1r - eic*c1i + gr*x1, c2i = er*c1i + eic*c1r + gi*x1;
        float c3r = er*c2r - eic*c2i + gr*x2, c3i = er*c2i + eic*c2r + gi*x2;
        float c4r = er*c3r - eic*c3i + gr*x3, c4i = er*c3i + eic*c3r + gi*x3;

        // warp inclusive scan of c4 with ratio E4
        float sr = c4r, si = c4i;
        { float ur=__shfl_up_sync(FULL,sr,1),  ui=__shfl_up_sync(FULL,si,1);
          if (lane>=1)  { sr += a0r*ur - a0i*ui; si += a0r*ui + a0i*ur; } }
        { float ur=__shfl_up_sync(FULL,sr,2),  ui=__shfl_up_sync(FULL,si,2);
          if (lane>=2)  { sr += a1r*ur - a1i*ui; si += a1r*ui + a1i*ur; } }
        { float ur=__shfl_up_sync(FULL,sr,4),  ui=__shfl_up_sync(FULL,si,4);
          if (lane>=4)  { sr += a2r*ur - a2i*ui; si += a2r*ui + a2i*ur; } }
        { float ur=__shfl_up_sync(FULL,sr,8),  ui=__shfl_up_sync(FULL,si,8);
          if (lane>=8)  { sr += a3r*ur - a3i*ui; si += a3r*ui + a3i*ur; } }
        { float ur=__shfl_up_sync(FULL,sr,16), ui=__shfl_up_sync(FULL,si,16);
          if (lane>=16) { sr += a4r*ur - a4i*ui; si += a4r*ui + a4i*ur; } }

        float hr = __shfl_up_sync(FULL, sr, 1);
        float hi = __shfl_up_sync(FULL, si, 1);
        if (lane == 0) { hr = 0.f; hi = 0.f; }

        // lane entry z = h + q*in
        float zr = hr + qr*inr - qi*ini;
        float zi = hi + qr*ini + qi*inr;

        // outputs o_k = c_k + e^k * z
        float o1r = c1r + er*zr  - eic*zi, o1i = c1i + er*zi  + eic*zr;
        float o2r = c2r + e2r*zr - e2i*zi, o2i = c2i + e2r*zi + e2i*zr;
        float o3r = c3r + e3r*zr - e3i*zi, o3i = c3i + e3r*zi + e3i*zr;
        float o4r = c4r + e4r*zr - e4i*zi, o4i = c4i + e4r*zi + e4i*zr;

        if (!REV) {
            *reinterpret_cast<float4*>(out_re + n0) = make_float4(o1r,o2r,o3r,o4r);
            *reinterpret_cast<float4*>(out_im + n0) = make_float4(o1i,o2i,o3i,o4i);
        } else {
            *reinterpret_cast<float4*>(out_re + (TT - 4 - n0)) = make_float4(o4r,o3r,o2r,o1r);
            *reinterpret_cast<float4*>(out_im + (TT - 4 - n0)) = make_float4(o4i,o3i,o2i,o1i);
        }

        // advance slice-entry state: in = T + E128*in  (T = inclusive total, lane 31)
        float Tr = __shfl_sync(FULL, sr, 31);
        float Ti = __shfl_sync(FULL, si, 31);
        float nr = Tr + e128r*inr - e128i*ini;
        float ni = Ti + e128r*ini + e128i*inr;
        inr = nr; ini = ni;
    }
}

__global__ void __launch_bounds__(WPB * 32)
kC(const float* __restrict__ audio, float* __restrict__ out)
{
    int lane = threadIdx.x & 31;
    int W = blockIdx.x * WPB + (threadIdx.x >> 5);
    int s = W / NSLICE;
    int j = W - s * NSLICE;
    int dir = s & 1, c = (s >> 1) & 63, b = s >> 7;

    const float* tb = g_ctab[c];
    const float* x = audio + (size_t)b * TT;
    float* base = out + (size_t)b * 4 * CC * TT;

    if (dir == 0) {
        sliceC<false>(x, base + (size_t)c * TT, base + (size_t)(CC + c) * TT,
                      s, j, lane, tb);
    } else {
        sliceC<true >(x, base + (size_t)(2*CC + c) * TT, base + (size_t)(3*CC + c) * TT,
                      s, j, lane, tb);
    }
}

extern "C" void kernel_launch(void* const* d_in, const int* in_sizes, int n_in,
                              void* d_out, int out_size)
{
    const float* audio = (const float*)d_in[0];
    const float* kre   = (const float*)d_in[1];
    const float* kim   = (const float*)d_in[2];
    float* out = (float*)d_out;
    (void)in_sizes; (void)n_in; (void)out_size;

    kprep<<<1, 64>>>(kre, kim);
    kA<<<NBLK, WPB * 32>>>(audio);
    kC<<<NBLK, WPB * 32>>>(audio, out);
}